// round 6
// baseline (speedup 1.0000x reference)
#include <cuda_runtime.h>
#include <cuda_bf16.h>

#define BSZ 16
#define SEQ 2048
#define DK  64
#define SCALE 0.125f   // 1/sqrt(64)

#define PROW_BYTES 144                    // 128B data + 16B pad (conflict-free)
#define PWIN_ROWS  127
#define PWIN_BYTES (PWIN_ROWS * PROW_BYTES)     // 18288
#define SMEM_BYTES (2*64*64*4 + 2*PWIN_BYTES)   // sK+sV (32KB) + 2 P windows = 69344

// Krelpos transposed + bf16: g_Pbf[t*DK + d] = bf16(Krelpos[d*SEQ + t])
__device__ __nv_bfloat16 g_Pbf[SEQ * DK];

__global__ void prep_krelpos_kernel(const float* __restrict__ Kp) {
    int idx = blockIdx.x * blockDim.x + threadIdx.x;
    if (idx < SEQ * DK) {
        int t = idx >> 6;
        int d = idx & 63;
        g_Pbf[idx] = __float2bfloat16_rn(Kp[d * SEQ + t]);
    }
}

// ---- packed f32x2 helpers ----
__device__ __forceinline__ unsigned long long pk2(float x, float y) {
    unsigned long long r;
    asm("mov.b64 %0, {%1, %2};" : "=l"(r) : "f"(x), "f"(y));
    return r;
}
__device__ __forceinline__ float2 upk(unsigned long long v) {
    float2 f;
    asm("mov.b64 {%0, %1}, %2;" : "=f"(f.x), "=f"(f.y) : "l"(v));
    return f;
}
// acc += q2 * (k2 + expand_bf16x2(pb))   [2 dims]
__device__ __forceinline__ void kp_fma2(unsigned long long& acc,
                                        unsigned long long q2,
                                        unsigned long long k2,
                                        unsigned int pb) {
    asm("{\n\t"
        ".reg .b32 lo, hi;\n\t"
        ".reg .b64 kp;\n\t"
        "prmt.b32 lo, %2, 0, 0x1044;\n\t"   // f32 bits of low bf16  (<<16)
        "prmt.b32 hi, %2, 0, 0x3244;\n\t"   // f32 bits of high bf16 (<<16)
        "mov.b64 kp, {lo, hi};\n\t"
        "add.rn.f32x2 kp, kp, %3;\n\t"
        "fma.rn.f32x2 %0, %1, kp, %0;\n\t"
        "}" : "+l"(acc) : "l"(q2), "r"(pb), "l"(k2));
}
__device__ __forceinline__ void fma2(unsigned long long& o,
                                     unsigned long long a, unsigned long long b) {
    asm("fma.rn.f32x2 %0, %1, %2, %0;" : "+l"(o) : "l"(a), "l"(b));
}
__device__ __forceinline__ void mul2(unsigned long long& o, unsigned long long a) {
    asm("mul.rn.f32x2 %0, %0, %1;" : "+l"(o) : "l"(a));
}

// One thread = one query row. Warps 0-1: tile p, warps 2-3: tile 31-p.
__global__ __launch_bounds__(128, 3) void attn_kernel(
    const float* __restrict__ Q, const float* __restrict__ K,
    const float* __restrict__ V, float* __restrict__ Out)
{
    extern __shared__ float smem[];
    float* sK = smem;                 // 64x64 f32
    float* sV = smem + 64 * 64;       // 64x64 f32
    char*  sP = (char*)(smem + 2 * 64 * 64);   // 2 windows of 127 rows x 144B (bf16)

    const int p    = blockIdx.x;      // 0..15
    const int b    = blockIdx.y;      // 0..15
    const int tid  = threadIdx.x;     // 0..127
    const int half = tid >> 6;
    const int j    = tid & 63;
    const int tileLo = p, tileHi = 31 - p;
    const int tile = half ? tileHi : tileLo;
    const int s    = tile * 64 + j;

    // Q row into packed registers
    const ulonglong2* qg = (const ulonglong2*)(Q + ((size_t)b * SEQ + s) * DK);
    unsigned long long q2[32];
#pragma unroll
    for (int i = 0; i < 16; i++) { ulonglong2 t = qg[i]; q2[2*i] = t.x; q2[2*i+1] = t.y; }

    unsigned long long o2[32];
#pragma unroll
    for (int i = 0; i < 32; i++) o2[i] = 0ull;
    float m = -1e30f, l = 0.0f;

    const int tEndSelf = s + 1;
    const int ctaEnd   = 2048 - 64 * p;   // hi tile bound (covers lo too)

    const float* Kb = K + (size_t)b * SEQ * DK;
    const float* Vb = V + (size_t)b * SEQ * DK;
    const uint4* Pg = (const uint4*)g_Pbf;          // row t at Pg + t*8 (128B rows)

    const int myPoff = half * PWIN_BYTES + (63 - j) * PROW_BYTES;

    for (int t0 = 0; t0 < ctaEnd; t0 += 64) {
        __syncthreads();
        // --- K/V tile load: 2048 float4 total, 128 threads -> 16 each
        {
            const float4* kg = (const float4*)(Kb + (size_t)t0 * DK);
            const float4* vg = (const float4*)(Vb + (size_t)t0 * DK);
#pragma unroll
            for (int i = 0; i < 8; i++) {
                int li = i * 128 + tid;
                ((float4*)sK)[li] = kg[li];
                ((float4*)sV)[li] = vg[li];
            }
        }
        // --- P window load: per half, 127 rows x 8 uint4 (guard row<=2047)
        {
            const int activeLo = (t0 <= 64 * tileLo + 63);
            const int baseLo = 1984 - 64 * tileLo + t0;
            const int baseHi = 64 * p + t0;            // = 1984 - 64*tileHi + t0
#pragma unroll
            for (int it = 0; it < 16; it++) {
                int idx = it * 128 + tid;
                if (idx >= 2 * 1016) break;
                int h   = idx >= 1016;
                int rem = idx - h * 1016;
                int r   = rem >> 3;
                int i   = rem & 7;
                if (h == 0 && !activeLo) continue;
                int srow = (h ? baseHi : baseLo) + r;
                if (srow > 2047) continue;
                *(uint4*)(sP + h * PWIN_BYTES + r * PROW_BYTES + i * 16) = Pg[srow * 8 + i];
            }
        }
        __syncthreads();

        const int tmax = tEndSelf - t0;
        if (tmax <= 0) continue;
        const int tlim = tmax < 64 ? tmax : 64;

#pragma unroll 1
        for (int tt = 0; tt < tlim; tt++) {
            const ulonglong2* kr = (const ulonglong2*)(sK + tt * 64);
            const uint4* pr = (const uint4*)(sP + myPoff + tt * PROW_BYTES);

            unsigned long long a0 = 0, a1 = 0, a2 = 0, a3 = 0;
#pragma unroll
            for (int i = 0; i < 8; i++) {
                uint4 pu = pr[i];
                ulonglong2 ka = kr[2 * i];
                ulonglong2 kb = kr[2 * i + 1];
                kp_fma2(a0, q2[4 * i + 0], ka.x, pu.x);
                kp_fma2(a1, q2[4 * i + 1], ka.y, pu.y);
                kp_fma2(a2, q2[4 * i + 2], kb.x, pu.z);
                kp_fma2(a3, q2[4 * i + 3], kb.y, pu.w);
            }
            float2 f0 = upk(a0), f1 = upk(a1), f2 = upk(a2), f3 = upk(a3);
            float sc = (((f0.x + f0.y) + (f1.x + f1.y)) +
                        ((f2.x + f2.y) + (f3.x + f3.y))) * SCALE;

            if (sc > m) {
                float corr = __expf(m - sc);
                l *= corr;
                unsigned long long c2 = pk2(corr, corr);
#pragma unroll
                for (int i = 0; i < 32; i++) mul2(o2[i], c2);
                m = sc;
            }
            float pe = __expf(sc - m);
            l += pe;
            unsigned long long pe2 = pk2(pe, pe);

            const ulonglong2* vr = (const ulonglong2*)(sV + tt * 64);
#pragma unroll
            for (int i = 0; i < 16; i++) {
                ulonglong2 v = vr[i];
                fma2(o2[2 * i + 0], pe2, v.x);
                fma2(o2[2 * i + 1], pe2, v.y);
            }
        }
    }

    const float inv = 1.0f / l;
    float4* og = (float4*)(Out + ((size_t)b * SEQ + s) * DK);
#pragma unroll
    for (int i = 0; i < 16; i++) {
        float2 a = upk(o2[2 * i]), c = upk(o2[2 * i + 1]);
        float4 r;
        r.x = a.x * inv; r.y = a.y * inv; r.z = c.x * inv; r.w = c.y * inv;
        og[i] = r;
    }
}

extern "C" void kernel_launch(void* const* d_in, const int* in_sizes, int n_in,
                              void* d_out, int out_size) {
    const float* Q  = (const float*)d_in[0];
    const float* K  = (const float*)d_in[1];
    const float* V  = (const float*)d_in[2];
    const float* Kp = (const float*)d_in[3];
    float* Out      = (float*)d_out;

    cudaFuncSetAttribute(attn_kernel, cudaFuncAttributeMaxDynamicSharedMemorySize,
                         SMEM_BYTES);

    prep_krelpos_kernel<<<(SEQ * DK + 255) / 256, 256>>>(Kp);
    dim3 grid(16, 16);
    attn_kernel<<<grid, 128, SMEM_BYTES>>>(Q, K, V, Out);
}

// round 8
// speedup vs baseline: 4.6825x; 4.6825x over previous
#include <cuda_runtime.h>
#include <cstdint>

#define NB  16
#define SEQ 2048
#define DKH 64
#define QSTR 68     // padded row stride (words) for 64-col tiles
#define PSTR 132    // padded row stride (words) for 128-col P tile

// ---------------- device scratch ----------------
__device__ uint32_t g_Pt[SEQ * DKH];                 // tf32 bits of Pt[c][d]
__device__ float    g_QP[(size_t)NB * SEQ * SEQ];    // bias matrix [b][s][c]

// ---------------- helpers ----------------
__device__ __forceinline__ float f2tf(float x) {
    uint32_t u; asm("cvt.rna.tf32.f32 %0, %1;" : "=r"(u) : "f"(x));
    return __uint_as_float(u);
}
__device__ __forceinline__ uint32_t fu(float x) { return __float_as_uint(x); }

__device__ __forceinline__ void mma_tf32(float d[4], const uint32_t a[4], const uint32_t b[2]) {
    asm volatile("mma.sync.aligned.m16n8k8.row.col.f32.tf32.tf32.f32 "
        "{%0,%1,%2,%3}, {%4,%5,%6,%7}, {%8,%9}, {%0,%1,%2,%3};"
        : "+f"(d[0]), "+f"(d[1]), "+f"(d[2]), "+f"(d[3])
        : "r"(a[0]), "r"(a[1]), "r"(a[2]), "r"(a[3]), "r"(b[0]), "r"(b[1]));
}

// Load 128x64 f32 tile row-major -> padded smem (stride QSTR), tf32-rounded.
__device__ __forceinline__ void ld_tile(float* dst, const float* src, int tid) {
#pragma unroll
    for (int k = 0; k < 8; k++) {
        int idx = k * 256 + tid;              // 2048 float4 total
        int row = idx >> 4, c4 = (idx & 15) * 4;
        float4 v = ((const float4*)src)[idx];
        float4 o = make_float4(f2tf(v.x), f2tf(v.y), f2tf(v.z), f2tf(v.w));
        *(float4*)(dst + row * QSTR + c4) = o;
    }
}

// ---------------- prep: Krelpos transpose + tf32 ----------------
__global__ void prep_kernel(const float* __restrict__ Kp) {
    int i = blockIdx.x * 256 + threadIdx.x;
    if (i < SEQ * DKH) {
        int c = i >> 6, d = i & 63;
        g_Pt[i] = fu(f2tf(Kp[d * SEQ + c]));
    }
}

// ---------------- bias GEMM: g_QP[b][s][c] = Q[b,s,:] . Pt[c,:] ----------------
#define BSMEM (2 * 128 * QSTR * 4)

__global__ void __launch_bounds__(256) bias_kernel(const float* __restrict__ Q) {
    const int si = blockIdx.x, ci = blockIdx.y, b = blockIdx.z;
    if (si + ci < 15) return;                 // never read under causal mask
    extern __shared__ float sm[];
    float* sQ = sm;
    float* sB = sm + 128 * QSTR;
    const int tid = threadIdx.x, w = tid >> 5, lane = tid & 31;
    const int g = lane >> 2, j = lane & 3;

    ld_tile(sQ, Q + ((size_t)b * SEQ + si * 128) * DKH, tid);
#pragma unroll
    for (int k = 0; k < 8; k++) {             // Pt tile: already tf32 bits
        int idx = k * 256 + tid;
        int row = idx >> 4, c4 = (idx & 15) * 4;
        *(uint4*)(sB + row * QSTR + c4) = ((const uint4*)(g_Pt + (size_t)ci * 128 * DKH))[idx];
    }
    __syncthreads();

    uint32_t qa[8][4];
#pragma unroll
    for (int k8 = 0; k8 < 8; k8++) {
        const float* ap = sQ + (w * 16 + g) * QSTR + k8 * 8 + j;
        qa[k8][0] = fu(ap[0]);
        qa[k8][1] = fu(ap[8 * QSTR]);
        qa[k8][2] = fu(ap[4]);
        qa[k8][3] = fu(ap[8 * QSTR + 4]);
    }
    float* o0 = g_QP + ((size_t)b * SEQ + si * 128 + w * 16 + g) * SEQ + ci * 128;
    float* o1 = o0 + (size_t)8 * SEQ;
#pragma unroll
    for (int n = 0; n < 16; n++) {
        float c[4] = {0.f, 0.f, 0.f, 0.f};
#pragma unroll
        for (int k8 = 0; k8 < 8; k8++) {
            const float* bp = sB + (n * 8 + g) * QSTR + k8 * 8 + j;
            uint32_t bb[2] = {fu(bp[0]), fu(bp[4])};
            mma_tf32(c, qa[k8], bb);
        }
        *(float2*)(o0 + n * 8 + 2 * j) = make_float2(c[0], c[1]);
        *(float2*)(o1 + n * 8 + 2 * j) = make_float2(c[2], c[3]);
    }
}

// ---------------- attention ----------------
#define ASMEM ((3 * 128 * QSTR + 128 * PSTR) * 4)   // 172032 bytes

__global__ void __launch_bounds__(256) attn_kernel(
    const float* __restrict__ Q, const float* __restrict__ K,
    const float* __restrict__ V, float* __restrict__ Out)
{
    extern __shared__ float sm[];
    float* sQ = sm;
    float* sK = sm + 128 * QSTR;
    float* sV = sm + 2 * 128 * QSTR;
    float* sP = sm + 3 * 128 * QSTR;
    const int tid = threadIdx.x, w = tid >> 5, lane = tid & 31;
    const int g = lane >> 2, j = lane & 3;
    const int b = blockIdx.x >> 3, q1 = blockIdx.x & 7;

    for (int item = 0; item < 2; item++) {
        const int qi = item ? (15 - q1) : q1;
        const int s0 = qi * 128;
        const int r0 = w * 16 + g;            // local rows r0, r0+8
        const int rg = s0 + r0;

        ld_tile(sQ, Q + ((size_t)b * SEQ + s0) * DKH, tid);
        __syncthreads();

        uint32_t qa[8][4];
#pragma unroll
        for (int k8 = 0; k8 < 8; k8++) {
            const float* ap = sQ + r0 * QSTR + k8 * 8 + j;
            qa[k8][0] = fu(ap[0]);
            qa[k8][1] = fu(ap[8 * QSTR]);
            qa[k8][2] = fu(ap[4]);
            qa[k8][3] = fu(ap[8 * QSTR + 4]);
        }

        float o[8][4];
#pragma unroll
        for (int n = 0; n < 8; n++) { o[n][0] = o[n][1] = o[n][2] = o[n][3] = 0.f; }
        float l0 = 0.f, l1 = 0.f;

        const float* bias0 = g_QP + ((size_t)b * SEQ + rg) * SEQ + (2047 - rg);
        const float* bias1 = g_QP + ((size_t)b * SEQ + rg + 8) * SEQ + (2047 - (rg + 8));

        for (int kt = 0; kt <= qi; kt++) {
            const int t0 = kt * 128;
            __syncthreads();    // prev iter's sP/sV reads done before overwrite
            ld_tile(sK, K + ((size_t)b * SEQ + t0) * DKH, tid);
            ld_tile(sV, V + ((size_t)b * SEQ + t0) * DKH, tid);
            __syncthreads();

            const bool diag = (kt == qi);
#pragma unroll
            for (int n = 0; n < 16; n++) {
                float c[4] = {0.f, 0.f, 0.f, 0.f};
#pragma unroll
                for (int k8 = 0; k8 < 8; k8++) {
                    const float* bp = sK + (n * 8 + g) * QSTR + k8 * 8 + j;
                    uint32_t bb[2] = {fu(bp[0]), fu(bp[4])};
                    mma_tf32(c, qa[k8], bb);
                }
                const int tc = t0 + n * 8 + 2 * j;
                float e0 = __expf((c[0] + bias0[tc]) * 0.125f);
                float e1 = __expf((c[1] + bias0[tc + 1]) * 0.125f);
                float e2 = __expf((c[2] + bias1[tc]) * 0.125f);
                float e3 = __expf((c[3] + bias1[tc + 1]) * 0.125f);
                if (diag) {
                    e0 = (tc     <= rg    ) ? e0 : 0.f;
                    e1 = (tc + 1 <= rg    ) ? e1 : 0.f;
                    e2 = (tc     <= rg + 8) ? e2 : 0.f;
                    e3 = (tc + 1 <= rg + 8) ? e3 : 0.f;
                }
                l0 += e0 + e1;
                l1 += e2 + e3;
                *(float2*)(sP + r0 * PSTR + n * 8 + 2 * j) =
                    make_float2(f2tf(e0), f2tf(e1));
                *(float2*)(sP + (r0 + 8) * PSTR + n * 8 + 2 * j) =
                    make_float2(f2tf(e2), f2tf(e3));
            }
            __syncthreads();

            // O += P (16 x 128) . V (128 x 64)
#pragma unroll
            for (int k8 = 0; k8 < 16; k8++) {
                const float* ap = sP + r0 * PSTR + k8 * 8 + j;
                uint32_t aa[4] = {fu(ap[0]), fu(ap[8 * PSTR]), fu(ap[4]), fu(ap[8 * PSTR + 4])};
#pragma unroll
                for (int n = 0; n < 8; n++) {
                    const float* bp = sV + (k8 * 8 + j) * QSTR + n * 8 + g;
                    uint32_t bb[2] = {fu(bp[0]), fu(bp[4 * QSTR])};
                    mma_tf32(o[n], aa, bb);
                }
            }
        }

        // row sums: reduce over the 4 threads of each row group
        l0 += __shfl_xor_sync(0xFFFFFFFFu, l0, 1);
        l0 += __shfl_xor_sync(0xFFFFFFFFu, l0, 2);
        l1 += __shfl_xor_sync(0xFFFFFFFFu, l1, 1);
        l1 += __shfl_xor_sync(0xFFFFFFFFu, l1, 2);
        const float i0 = 1.0f / l0, i1 = 1.0f / l1;

        float* og0 = Out + ((size_t)b * SEQ + rg) * DKH;
        float* og1 = og0 + 8 * DKH;
#pragma unroll
        for (int n = 0; n < 8; n++) {
            *(float2*)(og0 + n * 8 + 2 * j) = make_float2(o[n][0] * i0, o[n][1] * i0);
            *(float2*)(og1 + n * 8 + 2 * j) = make_float2(o[n][2] * i1, o[n][3] * i1);
        }
        __syncthreads();   // before next item overwrites sQ
    }
}

extern "C" void kernel_launch(void* const* d_in, const int* in_sizes, int n_in,
                              void* d_out, int out_size) {
    const float* Q  = (const float*)d_in[0];
    const float* K  = (const float*)d_in[1];
    const float* V  = (const float*)d_in[2];
    const float* Kp = (const float*)d_in[3];
    float* Out      = (float*)d_out;

    cudaFuncSetAttribute(bias_kernel, cudaFuncAttributeMaxDynamicSharedMemorySize, BSMEM);
    cudaFuncSetAttribute(attn_kernel, cudaFuncAttributeMaxDynamicSharedMemorySize, ASMEM);

    prep_kernel<<<(SEQ * DKH + 255) / 256, 256>>>(Kp);
    dim3 bg(16, 16, 16);
    bias_kernel<<<bg, 256, BSMEM>>>(Q);
    attn_kernel<<<128, 256, ASMEM>>>(Q, K, V, Out);
}

// round 10
// speedup vs baseline: 5.4801x; 1.1703x over previous
#include <cuda_runtime.h>
#include <cuda_bf16.h>
#include <cstdint>

#define NB  16
#define SEQ 2048
#define DKH 64
#define QSTR 68     // padded row stride (words) for 64-col tiles
#define PSTR 132    // padded row stride (words) for 128-col P tile

// ---------------- device scratch ----------------
__device__ uint32_t g_Pt[SEQ * DKH];                        // tf32 bits of Pt[c][d]
__device__ __nv_bfloat16 g_QPb[(size_t)NB * SEQ * SEQ];     // shifted bias [b][s][t]
__device__ int g_ctr;                                        // persistent work counter

// ---------------- helpers ----------------
__device__ __forceinline__ float f2tf(float x) {
    uint32_t u; asm("cvt.rna.tf32.f32 %0, %1;" : "=r"(u) : "f"(x));
    return __uint_as_float(u);
}
__device__ __forceinline__ uint32_t fu(float x) { return __float_as_uint(x); }

__device__ __forceinline__ void mma_tf32(float d[4], const uint32_t a[4], const uint32_t b[2]) {
    asm volatile("mma.sync.aligned.m16n8k8.row.col.f32.tf32.tf32.f32 "
        "{%0,%1,%2,%3}, {%4,%5,%6,%7}, {%8,%9}, {%0,%1,%2,%3};"
        : "+f"(d[0]), "+f"(d[1]), "+f"(d[2]), "+f"(d[3])
        : "r"(a[0]), "r"(a[1]), "r"(a[2]), "r"(a[3]), "r"(b[0]), "r"(b[1]));
}

// direct load 128x64 f32 tile -> padded smem (tf32-rounded)
__device__ __forceinline__ void ld_tile(float* dst, const float* src, int tid) {
#pragma unroll
    for (int k = 0; k < 8; k++) {
        int idx = k * 256 + tid;
        int row = idx >> 4, c4 = (idx & 15) * 4;
        float4 v = ((const float4*)src)[idx];
        *(float4*)(dst + row * QSTR + c4) =
            make_float4(f2tf(v.x), f2tf(v.y), f2tf(v.z), f2tf(v.w));
    }
}
// staged: gmem -> regs
__device__ __forceinline__ void ldg8(float4 v[8], const float* src, int tid) {
#pragma unroll
    for (int k = 0; k < 8; k++) v[k] = ((const float4*)src)[k * 256 + tid];
}
// staged: regs -> smem (tf32-rounded)
__device__ __forceinline__ void sts8(float* dst, const float4 v[8], int tid) {
#pragma unroll
    for (int k = 0; k < 8; k++) {
        int idx = k * 256 + tid;
        int row = idx >> 4, c4 = (idx & 15) * 4;
        *(float4*)(dst + row * QSTR + c4) =
            make_float4(f2tf(v[k].x), f2tf(v[k].y), f2tf(v[k].z), f2tf(v[k].w));
    }
}

// ---------------- prep: Krelpos transpose + tf32; reset work counter ----------------
__global__ void prep_kernel(const float* __restrict__ Kp) {
    int i = blockIdx.x * 256 + threadIdx.x;
    if (i == 0) g_ctr = 0;
    if (i < SEQ * DKH) {
        int c = i >> 6, d = i & 63;
        g_Pt[i] = fu(f2tf(Kp[d * SEQ + c]));
    }
}

// ---------------- bias GEMM -> shifted bf16: g_QPb[b][s][t] = Q[b,s,:].Pt[2047-s+t,:]
#define BSMEM (2 * 128 * QSTR * 4)

__global__ void __launch_bounds__(256) bias_kernel(const float* __restrict__ Q) {
    const int si = blockIdx.x, ci = blockIdx.y, b = blockIdx.z;
    if (si + ci < 15) return;                 // entirely t<0 under causal mask
    extern __shared__ float sm[];
    float* sQ = sm;
    float* sB = sm + 128 * QSTR;
    const int tid = threadIdx.x, w = tid >> 5, lane = tid & 31;
    const int g = lane >> 2, j = lane & 3;

    ld_tile(sQ, Q + ((size_t)b * SEQ + si * 128) * DKH, tid);
#pragma unroll
    for (int k = 0; k < 8; k++) {             // Pt tile already tf32 bits
        int idx = k * 256 + tid;
        int row = idx >> 4, c4 = (idx & 15) * 4;
        *(uint4*)(sB + row * QSTR + c4) = ((const uint4*)(g_Pt + (size_t)ci * 128 * DKH))[idx];
    }
    __syncthreads();

    uint32_t qa[8][4];
#pragma unroll
    for (int k8 = 0; k8 < 8; k8++) {
        const float* ap = sQ + (w * 16 + g) * QSTR + k8 * 8 + j;
        qa[k8][0] = fu(ap[0]);
        qa[k8][1] = fu(ap[8 * QSTR]);
        qa[k8][2] = fu(ap[4]);
        qa[k8][3] = fu(ap[8 * QSTR + 4]);
    }
    const int sr = si * 128 + w * 16 + g;     // global s of row 0 of this thread
    __nv_bfloat16* row0 = g_QPb + ((size_t)b * SEQ + sr) * SEQ;
    __nv_bfloat16* row1 = row0 + (size_t)8 * SEQ;
    const int tb0 = ci * 128 + 2 * j + sr - 2047;   // shifted t of col 2j, row sr
    const int tb1 = tb0 + 8;                         // for row sr+8
#pragma unroll
    for (int n = 0; n < 16; n++) {
        float c[4] = {0.f, 0.f, 0.f, 0.f};
#pragma unroll
        for (int k8 = 0; k8 < 8; k8++) {
            const float* bp = sB + (n * 8 + g) * QSTR + k8 * 8 + j;
            uint32_t bb[2] = {fu(bp[0]), fu(bp[4])};
            mma_tf32(c, qa[k8], bb);
        }
        const int t0 = tb0 + n * 8;
        if (t0 >= 0)     row0[t0]     = __float2bfloat16_rn(c[0]);
        if (t0 + 1 >= 0) row0[t0 + 1] = __float2bfloat16_rn(c[1]);
        const int t1 = tb1 + n * 8;
        if (t1 >= 0)     row1[t1]     = __float2bfloat16_rn(c[2]);
        if (t1 + 1 >= 0) row1[t1 + 1] = __float2bfloat16_rn(c[3]);
    }
}

// ---------------- attention (persistent, pipelined) ----------------
#define ASMEM ((3 * 128 * QSTR + 128 * PSTR) * 4)   // 172032 bytes

__global__ void __launch_bounds__(256, 1) attn_kernel(
    const float* __restrict__ Q, const float* __restrict__ K,
    const float* __restrict__ V, float* __restrict__ Out)
{
    extern __shared__ float sm[];
    float* sQ = sm;
    float* sK = sm + 128 * QSTR;
    float* sV = sm + 2 * 128 * QSTR;
    float* sP = sm + 3 * 128 * QSTR;
    __shared__ int sWork;
    const int tid = threadIdx.x, w = tid >> 5, lane = tid & 31;
    const int g = lane >> 2, j = lane & 3;

    for (;;) {
        if (tid == 0) sWork = atomicAdd(&g_ctr, 1);
        __syncthreads();
        const int idx = sWork;
        if (idx >= 256) return;
        const int qi = 15 - (idx >> 4);       // LPT: big items first
        const int b  = idx & 15;

        const int s0 = qi * 128;
        const int r0 = w * 16 + g;
        const int rg = s0 + r0;
        const float* Kb = K + (size_t)b * SEQ * DKH;
        const float* Vb = V + (size_t)b * SEQ * DKH;
        const __nv_bfloat16* bias0 = g_QPb + ((size_t)b * SEQ + rg) * SEQ;
        const __nv_bfloat16* bias1 = bias0 + (size_t)8 * SEQ;

        float4 stage[8];
        ldg8(stage, Kb + (size_t)0, tid);                    // K(0)
        ld_tile(sQ, Q + ((size_t)b * SEQ + s0) * DKH, tid);  // Q tile
        sts8(sK, stage, tid);
        __syncthreads();

        uint32_t qa[8][4];
#pragma unroll
        for (int k8 = 0; k8 < 8; k8++) {
            const float* ap = sQ + r0 * QSTR + k8 * 8 + j;
            qa[k8][0] = fu(ap[0]);
            qa[k8][1] = fu(ap[8 * QSTR]);
            qa[k8][2] = fu(ap[4]);
            qa[k8][3] = fu(ap[8 * QSTR + 4]);
        }

        float o[8][4];
#pragma unroll
        for (int n = 0; n < 8; n++) { o[n][0] = o[n][1] = o[n][2] = o[n][3] = 0.f; }
        float l0 = 0.f, l1 = 0.f;

        for (int kt = 0; kt <= qi; kt++) {
            const int t0 = kt * 128;
            // prefetch this tile's bias rows (aligned bf16 pairs), then V
            uint32_t bz0[16], bz1[16];
#pragma unroll
            for (int n = 0; n < 16; n++) {
                bz0[n] = *(const uint32_t*)(bias0 + t0 + n * 8 + 2 * j);
                bz1[n] = *(const uint32_t*)(bias1 + t0 + n * 8 + 2 * j);
            }
            ldg8(stage, Vb + (size_t)t0 * DKH, tid);          // V(kt) -> regs

            const bool diag = (kt == qi);
#pragma unroll
            for (int n = 0; n < 16; n++) {
                float c[4] = {0.f, 0.f, 0.f, 0.f};
#pragma unroll
                for (int k8 = 0; k8 < 8; k8++) {
                    const float* bp = sK + (n * 8 + g) * QSTR + k8 * 8 + j;
                    uint32_t bb[2] = {fu(bp[0]), fu(bp[4])};
                    mma_tf32(c, qa[k8], bb);
                }
                const float b00 = __uint_as_float(bz0[n] << 16);
                const float b01 = __uint_as_float(bz0[n] & 0xFFFF0000u);
                const float b10 = __uint_as_float(bz1[n] << 16);
                const float b11 = __uint_as_float(bz1[n] & 0xFFFF0000u);
                float e0 = __expf((c[0] + b00) * 0.125f);
                float e1 = __expf((c[1] + b01) * 0.125f);
                float e2 = __expf((c[2] + b10) * 0.125f);
                float e3 = __expf((c[3] + b11) * 0.125f);
                if (diag) {
                    const int tc = t0 + n * 8 + 2 * j;
                    e0 = (tc     <= rg    ) ? e0 : 0.f;
                    e1 = (tc + 1 <= rg    ) ? e1 : 0.f;
                    e2 = (tc     <= rg + 8) ? e2 : 0.f;
                    e3 = (tc + 1 <= rg + 8) ? e3 : 0.f;
                }
                l0 += e0 + e1;
                l1 += e2 + e3;
                *(float2*)(sP + r0 * PSTR + n * 8 + 2 * j) = make_float2(f2tf(e0), f2tf(e1));
                *(float2*)(sP + (r0 + 8) * PSTR + n * 8 + 2 * j) = make_float2(f2tf(e2), f2tf(e3));
            }
            sts8(sV, stage, tid);                             // V regs -> smem
            __syncthreads();      // S done (sK free), sV+sP ready

            if (kt < qi) ldg8(stage, Kb + (size_t)(t0 + 128) * DKH, tid);  // K(kt+1)

            // O += P (16x128) . V (128x64)
#pragma unroll
            for (int k8 = 0; k8 < 16; k8++) {
                const float* ap = sP + r0 * PSTR + k8 * 8 + j;
                uint32_t aa[4] = {fu(ap[0]), fu(ap[8 * PSTR]), fu(ap[4]), fu(ap[8 * PSTR + 4])};
#pragma unroll
                for (int n = 0; n < 8; n++) {
                    const float* bp = sV + (k8 * 8 + j) * QSTR + n * 8 + g;
                    uint32_t bb[2] = {fu(bp[0]), fu(bp[4 * QSTR])};
                    mma_tf32(o[n], aa, bb);
                }
            }
            if (kt < qi) sts8(sK, stage, tid);                // K(kt+1) -> smem
            __syncthreads();      // sK ready; sV/sP reusable
        }

        l0 += __shfl_xor_sync(0xFFFFFFFFu, l0, 1);
        l0 += __shfl_xor_sync(0xFFFFFFFFu, l0, 2);
        l1 += __shfl_xor_sync(0xFFFFFFFFu, l1, 1);
        l1 += __shfl_xor_sync(0xFFFFFFFFu, l1, 2);
        const float i0 = 1.0f / l0, i1 = 1.0f / l1;

        float* og0 = Out + ((size_t)b * SEQ + rg) * DKH;
        float* og1 = og0 + 8 * DKH;
#pragma unroll
        for (int n = 0; n < 8; n++) {
            *(float2*)(og0 + n * 8 + 2 * j) = make_float2(o[n][0] * i0, o[n][1] * i0);
            *(float2*)(og1 + n * 8 + 2 * j) = make_float2(o[n][2] * i1, o[n][3] * i1);
        }
        __syncthreads();          // protect sWork + smem before next item
    }
}

extern "C" void kernel_launch(void* const* d_in, const int* in_sizes, int n_in,
                              void* d_out, int out_size) {
    const float* Q  = (const float*)d_in[0];
    const float* K  = (const float*)d_in[1];
    const float* V  = (const float*)d_in[2];
    const float* Kp = (const float*)d_in[3];
    float* Out      = (float*)d_out;

    cudaFuncSetAttribute(bias_kernel, cudaFuncAttributeMaxDynamicSharedMemorySize, BSMEM);
    cudaFuncSetAttribute(attn_kernel, cudaFuncAttributeMaxDynamicSharedMemorySize, ASMEM);

    prep_kernel<<<(SEQ * DKH + 255) / 256, 256>>>(Kp);
    dim3 bg(16, 16, 16);
    bias_kernel<<<bg, 256, BSMEM>>>(Q);
    attn_kernel<<<148, 256, ASMEM>>>(Q, K, V, Out);
}